// round 1
// baseline (speedup 1.0000x reference)
#include <cuda_runtime.h>
#include <cstddef>

#define M_ROWS  160000   // n = N_EDGES (GCN runs over edge-embedding rows)
#define NE      160000   // number of edges
#define NN      10000    // N_NODES (row/col index range)
#define HID     300
#define LDIM    32

// ---------------- scratch (static __device__, allocation-free) ----------------
__device__ float g_bufA[(size_t)M_ROWS * HID];   // 192 MB
__device__ float g_bufB[(size_t)M_ROWS * HID];   // 192 MB
__device__ float g_hwS[(size_t)NN * HID];        // 12 MB: raw hw for rows < NN
__device__ int   g_cnt[NN];                      // in-degree counts (deg = cnt+1)
__device__ float g_colsum[HID + 4];              // column sums for mean readout

typedef unsigned long long ull;

__device__ __forceinline__ ull dup2(float x) {
    union { float2 f; ull u; } v; v.f = make_float2(x, x); return v.u;
}
__device__ __forceinline__ float2 unpack2(ull u) {
    union { float2 f; ull uu; } v; v.uu = u; return v.f;
}
#define FMA2(d, a, b, c) asm("fma.rn.f32x2 %0, %1, %2, %3;" : "=l"(d) : "l"(a), "l"(b), "l"(c))

// ---------------- small prep kernels ----------------
__global__ void k_init() {
    int i = blockIdx.x * blockDim.x + threadIdx.x;
    if (i < NN)  g_cnt[i] = 0;
    if (i < HID) g_colsum[i] = 0.0f;
}

__global__ void k_count(const int* __restrict__ ei) {
    int e = blockIdx.x * blockDim.x + threadIdx.x;
    if (e < NE) atomicAdd(&g_cnt[ei[NE + e]], 1);
}

// e = edge_attr @ edge_w + edge_b  -> g_bufA rows (stride HID, cols [0,32))
__global__ void k_edge_embed(const float* __restrict__ attr,
                             const float* __restrict__ w,
                             const float* __restrict__ b) {
    int idx = blockIdx.x * blockDim.x + threadIdx.x;
    if (idx >= NE * LDIM) return;
    int e = idx >> 5, j = idx & 31;
    float a0 = attr[e * 3 + 0], a1 = attr[e * 3 + 1], a2 = attr[e * 3 + 2];
    float s = b[j] + a0 * w[j] + a1 * w[32 + j] + a2 * w[64 + j];
    g_bufA[(size_t)e * HID + j] = s;
}

// ---------------- main GEMM ----------------
// C[m][n] = act(A[m][:K]) @ B[K][HID] ;  out = self_norm(m)*C + bias ; hwS[m<NN] = C
// BM=256, BN=64, BK=8, 256 threads, 8x8 thread tile via f32x2 packed FMA.
template <int RELU_A>
__global__ __launch_bounds__(256)
void k_gemm(const float* __restrict__ A, const float* __restrict__ B,
            const float* __restrict__ bias, float* __restrict__ out, int K) {
    const int tid = threadIdx.x;
    const int m0  = blockIdx.x * 256;
    const int n0  = blockIdx.y * 64;

    __shared__ ull   As2[8][256];    // A values duplicated into both f32x2 lanes
    __shared__ float Bs[8][64];

    ull acc[8][4];
#pragma unroll
    for (int i = 0; i < 8; i++)
#pragma unroll
        for (int j = 0; j < 4; j++) acc[i][j] = 0ULL;

    const int rg = tid >> 3;          // 0..31 row group (8 rows each)
    const int cg = tid & 7;           // 0..7 col group (8 cols each)
    const int la_m = tid >> 1;        // A loader: row 0..127 (+128 for second)
    const int la_k = (tid & 1) * 4;   // A loader: k offset 0 or 4
    const int lb_k = tid >> 5;        // B loader: k 0..7
    const int lb_n = (tid & 31) * 2;  // B loader: n 0..62 (even)

    for (int k0 = 0; k0 < K; k0 += 8) {
        // --- load A tile (256 x 8), relu on load, dup-pack into smem ---
#pragma unroll
        for (int i = 0; i < 2; i++) {
            int m = m0 + la_m + i * 128;
            float4 v;
            if (k0 + la_k + 3 < K) {
                v = *reinterpret_cast<const float4*>(A + (size_t)m * HID + k0 + la_k);
            } else {
                float t[4] = {0.f, 0.f, 0.f, 0.f};
#pragma unroll
                for (int u = 0; u < 4; u++) {
                    int kk = k0 + la_k + u;
                    if (kk < K) t[u] = A[(size_t)m * HID + kk];
                }
                v = make_float4(t[0], t[1], t[2], t[3]);
            }
            if (RELU_A) {
                v.x = fmaxf(v.x, 0.f); v.y = fmaxf(v.y, 0.f);
                v.z = fmaxf(v.z, 0.f); v.w = fmaxf(v.w, 0.f);
            }
            As2[la_k + 0][la_m + i * 128] = dup2(v.x);
            As2[la_k + 1][la_m + i * 128] = dup2(v.y);
            As2[la_k + 2][la_m + i * 128] = dup2(v.z);
            As2[la_k + 3][la_m + i * 128] = dup2(v.w);
        }
        // --- load B tile (8 x 64) ---
        {
            int kk = k0 + lb_k;
            float2 v = make_float2(0.f, 0.f);
            if (kk < K) {
                int n = n0 + lb_n;
                if (n + 1 < HID)
                    v = *reinterpret_cast<const float2*>(B + (size_t)kk * HID + n);
                else if (n < HID)
                    v.x = B[(size_t)kk * HID + n];
            }
            Bs[lb_k][lb_n]     = v.x;
            Bs[lb_k][lb_n + 1] = v.y;
        }
        __syncthreads();

#pragma unroll
        for (int kk = 0; kk < 8; kk++) {
            ull a[8];
            const ull* arow = &As2[kk][rg * 8];
#pragma unroll
            for (int i = 0; i < 8; i++) a[i] = arow[i];
            ull b[4];
            const ull* brow = reinterpret_cast<const ull*>(&Bs[kk][0]) + cg * 4;
#pragma unroll
            for (int j = 0; j < 4; j++) b[j] = brow[j];
#pragma unroll
            for (int i = 0; i < 8; i++)
#pragma unroll
                for (int j = 0; j < 4; j++)
                    FMA2(acc[i][j], a[i], b[j], acc[i][j]);
        }
        __syncthreads();
    }

    // --- epilogue: out = self_norm*hw + bias ; stash raw hw for rows < NN ---
#pragma unroll
    for (int i = 0; i < 8; i++) {
        int m = m0 + rg * 8 + i;
        float sn = 1.0f;
        if (m < NN) {
            float r = rsqrtf((float)(g_cnt[m] + 1));
            sn = r * r;
        }
        float* orow = out + (size_t)m * HID;
        float* hrow = g_hwS + (size_t)m * HID;
#pragma unroll
        for (int j = 0; j < 4; j++) {
            int nn = n0 + cg * 8 + j * 2;
            if (nn < HID) {
                float2 c  = unpack2(acc[i][j]);
                float2 b2 = *reinterpret_cast<const float2*>(bias + nn);
                float2 o  = make_float2(sn * c.x + b2.x, sn * c.y + b2.y);
                *reinterpret_cast<float2*>(orow + nn) = o;
                if (m < NN) *reinterpret_cast<float2*>(hrow + nn) = c;
            }
        }
    }
}

// ---------------- sparse scatter: out[col] += norm(e) * hw[row] ----------------
__global__ void k_scatter(const int* __restrict__ ei, float* __restrict__ out) {
    int warp = (blockIdx.x * blockDim.x + threadIdx.x) >> 5;
    int lane = threadIdx.x & 31;
    if (warp >= NE) return;
    int r = ei[warp], c = ei[NE + warp];
    float norm = rsqrtf((float)(g_cnt[r] + 1)) * rsqrtf((float)(g_cnt[c] + 1));
    const float* src = g_hwS + (size_t)r * HID;
    float*       dst = out   + (size_t)c * HID;
    for (int j = lane; j < HID; j += 32)
        atomicAdd(dst + j, norm * src[j]);
}

// ---------------- readout: column sums of relu(h) ----------------
__global__ void k_mean(const float* __restrict__ h) {
    int j = threadIdx.x;
    if (j >= HID) return;
    size_t r0 = (size_t)blockIdx.x * 256;
    size_t r1 = r0 + 256;
    if (r1 > (size_t)M_ROWS) r1 = (size_t)M_ROWS;
    float acc = 0.f;
    for (size_t r = r0; r < r1; r++)
        acc += fmaxf(h[r * HID + j], 0.f);
    atomicAdd(&g_colsum[j], acc);
}

// ---------------- head: mean -> lin1 -> relu -> lin2 ----------------
__global__ void k_head(const float* __restrict__ w1, const float* __restrict__ b1,
                       const float* __restrict__ w2, const float* __restrict__ b2,
                       float* __restrict__ out) {
    __shared__ float g[HID];
    __shared__ float t1[32];
    int t = threadIdx.x;
    if (t < HID) g[t] = g_colsum[t] * (1.0f / (float)M_ROWS);
    __syncthreads();
    if (t < 32) {
        float a = b1[t];
        for (int j = 0; j < HID; j++) a += g[j] * w1[j * 32 + t];
        t1[t] = fmaxf(a, 0.f);
    }
    __syncthreads();
    if (t < 2) {
        float a = b2[t];
        for (int k = 0; k < 32; k++) a += t1[k] * w2[k * 2 + t];
        out[t] = a;
    }
}

// ---------------- launch ----------------
extern "C" void kernel_launch(void* const* d_in, const int* in_sizes, int n_in,
                              void* d_out, int out_size) {
    // metadata order: x, edge_index, edge_attr, batch, node_w, node_b, edge_w,
    //                 edge_b, gcn0_w, gcn0_b, gcn_w, gcn_b, lin1_w, lin1_b,
    //                 lin2_w, lin2_b
    const int*   ei        = (const int*)d_in[1];
    const float* edge_attr = (const float*)d_in[2];
    const float* edge_w    = (const float*)d_in[6];
    const float* edge_b    = (const float*)d_in[7];
    const float* gcn0_w    = (const float*)d_in[8];
    const float* gcn0_b    = (const float*)d_in[9];
    const float* gcn_w     = (const float*)d_in[10];
    const float* gcn_b     = (const float*)d_in[11];
    const float* lin1_w    = (const float*)d_in[12];
    const float* lin1_b    = (const float*)d_in[13];
    const float* lin2_w    = (const float*)d_in[14];
    const float* lin2_b    = (const float*)d_in[15];
    float* out = (float*)d_out;

    float *bufA = nullptr, *bufB = nullptr;
    cudaGetSymbolAddress((void**)&bufA, g_bufA);
    cudaGetSymbolAddress((void**)&bufB, g_bufB);

    k_init<<<(NN + 255) / 256, 256>>>();
    k_count<<<(NE + 255) / 256, 256>>>(ei);
    k_edge_embed<<<(NE * LDIM + 255) / 256, 256>>>(edge_attr, edge_w, edge_b);

    dim3 ggrid(M_ROWS / 256, (HID + 63) / 64);

    // layer 0: K=32, no relu on input
    k_gemm<0><<<ggrid, 256>>>(bufA, gcn0_w, gcn0_b, bufB, LDIM);
    k_scatter<<<NE / 8, 256>>>(ei, bufB);

    // layers 1..4: K=300, relu on input (deferred from previous layer)
    for (int l = 1; l < 5; l++) {
        const float* in = (l % 2 == 1) ? bufB : bufA;
        float*       o  = (l % 2 == 1) ? bufA : bufB;
        k_gemm<1><<<ggrid, 256>>>(in, gcn_w + (size_t)(l - 1) * HID * HID,
                                  gcn_b + (size_t)(l - 1) * HID, o, HID);
        k_scatter<<<NE / 8, 256>>>(ei, o);
    }

    // final h is in bufB (l=4 writes bufB); relu fused into the mean
    k_mean<<<M_ROWS / 256, 320>>>(bufB);
    k_head<<<1, 320>>>(lin1_w, lin1_b, lin2_w, lin2_b, out);
}

// round 3
// speedup vs baseline: 2.2899x; 2.2899x over previous
#include <cuda_runtime.h>
#include <cstdint>
#include <cstddef>

#define NE    160000
#define NN    10000
#define HID   300
#define PAD   320
#define LDIM  32
#define MRWS  160000

// ---------------- scratch (static __device__, allocation-free) ----------------
__device__ float g_bufA[(size_t)MRWS * PAD];   // 204.8 MB
__device__ float g_bufB[(size_t)MRWS * PAD];   // 204.8 MB
__device__ float g_hwS[(size_t)NN * PAD];      // 12.8 MB raw hw, rows < NN
__device__ int   g_cnt[NN];
__device__ float g_dinv[NN];
__device__ int   g_rowptr[NN + 1];
__device__ int   g_fill[NN];
__device__ int   g_eid[NE];
__device__ int   g_src[NE];
__device__ float g_val[NE];
__device__ float g_part[625 * PAD];

// ---------------- tf32 helpers (family-agnostic PTX only) ----------------
__device__ __forceinline__ uint32_t cvt_tf32(float x) {
    uint32_t u; asm("cvt.rna.tf32.f32 %0, %1;" : "=r"(u) : "f"(x)); return u;
}
#define MMA_TF32(c, a, b)                                                     \
    asm volatile("mma.sync.aligned.m16n8k8.row.col.f32.tf32.tf32.f32 "        \
        "{%0,%1,%2,%3}, {%4,%5,%6,%7}, {%8,%9}, {%0,%1,%2,%3};"               \
        : "+f"((c)[0]), "+f"((c)[1]), "+f"((c)[2]), "+f"((c)[3])              \
        : "r"((a)[0]), "r"((a)[1]), "r"((a)[2]), "r"((a)[3]),                 \
          "r"((b)[0]), "r"((b)[1]))

// ---------------- prep kernels ----------------
__global__ void k_init() {
    int i = blockIdx.x * blockDim.x + threadIdx.x;
    if (i < NN) { g_cnt[i] = 0; g_fill[i] = 0; }
}
__global__ void k_count(const int* __restrict__ ei) {
    int e = blockIdx.x * blockDim.x + threadIdx.x;
    if (e < NE) atomicAdd(&g_cnt[ei[NE + e]], 1);
}
__global__ void k_dinv() {
    int i = blockIdx.x * blockDim.x + threadIdx.x;
    if (i < NN) g_dinv[i] = rsqrtf((float)(g_cnt[i] + 1));
}
__global__ void k_scan() {
    __shared__ int sm[1024];
    int t = threadIdx.x;
    int v[10]; int loc = 0;
#pragma unroll
    for (int u = 0; u < 10; u++) {
        int idx = t * 10 + u;
        v[u] = (idx < NN) ? g_cnt[idx] : 0;
        loc += v[u];
    }
    sm[t] = loc; __syncthreads();
    for (int off = 1; off < 1024; off <<= 1) {
        int add = (t >= off) ? sm[t - off] : 0;
        __syncthreads();
        sm[t] += add;
        __syncthreads();
    }
    int run = sm[t] - loc;
#pragma unroll
    for (int u = 0; u < 10; u++) {
        int idx = t * 10 + u;
        if (idx < NN) { g_rowptr[idx] = run; run += v[u]; }
    }
    if (t == 0) g_rowptr[NN] = NE;
}
__global__ void k_fillidx(const int* __restrict__ ei) {
    int e = blockIdx.x * blockDim.x + threadIdx.x;
    if (e >= NE) return;
    int c = ei[NE + e];
    int p = atomicAdd(&g_fill[c], 1);
    g_eid[g_rowptr[c] + p] = e;
}
// deterministic per-node ordering: sort edge ids ascending
__global__ void k_sortnode(const int* __restrict__ ei) {
    int i = blockIdx.x * blockDim.x + threadIdx.x;
    if (i >= NN) return;
    int s = g_rowptr[i], d = g_rowptr[i + 1] - s;
    if (d <= 128) {
        int ids[128];
        for (int q = 0; q < d; q++) ids[q] = g_eid[s + q];
        for (int q = 1; q < d; q++) {
            int key = ids[q], p = q - 1;
            while (p >= 0 && ids[p] > key) { ids[p + 1] = ids[p]; p--; }
            ids[p + 1] = key;
        }
        for (int q = 0; q < d; q++) g_eid[s + q] = ids[q];
    } else {
        for (int q = 1; q < d; q++) {   // rare fallback, in-place, deterministic
            int key = g_eid[s + q], p = q - 1;
            while (p >= 0 && g_eid[s + p] > key) { g_eid[s + p + 1] = g_eid[s + p]; p--; }
            g_eid[s + p + 1] = key;
        }
    }
    float di = g_dinv[i];
    for (int q = 0; q < d; q++) {
        int e = g_eid[s + q];
        int r = ei[e];
        g_src[s + q] = r;
        g_val[s + q] = g_dinv[r] * di;
    }
}
__global__ void k_edge_embed(const float* __restrict__ attr,
                             const float* __restrict__ w,
                             const float* __restrict__ b) {
    int idx = blockIdx.x * blockDim.x + threadIdx.x;
    if (idx >= NE * LDIM) return;
    int e = idx >> 5, j = idx & 31;
    float a0 = attr[e * 3 + 0], a1 = attr[e * 3 + 1], a2 = attr[e * 3 + 2];
    g_bufA[(size_t)e * PAD + j] = b[j] + a0 * w[j] + a1 * w[32 + j] + a2 * w[64 + j];
}

// ---------------- tf32 mma.sync GEMM ----------------
// BM=128, BN=64, BK=32, 256 threads (8 warps, 4x2), warp tile 32x32.
// out = self_norm(m)*C + bias ; raw C stashed to g_hwS for m < NN.
// B split hi/lo (exact tf32 truncation + residual), both accumulated.
#define AS_STRIDE 36
#define BS_STRIDE 68
#define AS_BUF    (128 * AS_STRIDE)          // 4608 words
#define BS_BUF    (32 * BS_STRIDE)           // 2176 words
#define BH_OFF    (2 * AS_BUF)               // 9216
#define BL_OFF    (BH_OFF + 2 * BS_BUF)      // 13568
#define SM_WORDS  (BL_OFF + 2 * BS_BUF)      // 17920 words = 71680 B

template <int RELU>
__global__ __launch_bounds__(256)
void k_gemm(const float* __restrict__ A, const float* __restrict__ W,
            const float* __restrict__ bias, float* __restrict__ out,
            int Kchunks, int Ktot) {
    extern __shared__ uint32_t smu[];
    const int tid  = threadIdx.x;
    const int wid  = tid >> 5, lane = tid & 31;
    const int wm   = wid & 3, wn = wid >> 2;
    const size_t m0 = (size_t)blockIdx.x * 128;
    const int    n0 = blockIdx.y * 64;

    float acc[2][4][4];
#pragma unroll
    for (int t = 0; t < 2; t++)
#pragma unroll
        for (int j = 0; j < 4; j++)
#pragma unroll
            for (int q = 0; q < 4; q++) acc[t][j][q] = 0.f;

    float4 pA[4], pB[2];
    const int arow = tid >> 3, ac4 = (tid & 7) * 4;
    const int bk   = tid >> 4, bn4 = (tid & 15) * 4;

    // prefetch chunk c into registers
    auto ldg_chunk = [&](int c) {
        int k0 = c * 32;
#pragma unroll
        for (int p = 0; p < 4; p++)
            pA[p] = *(const float4*)(A + (m0 + arow + p * 32) * PAD + k0 + ac4);
#pragma unroll
        for (int p = 0; p < 2; p++) {
            int k = k0 + bk + p * 16;
            int n = n0 + bn4;
            if (k < Ktot && n < HID)
                pB[p] = *(const float4*)(W + (size_t)k * HID + n);
            else
                pB[p] = make_float4(0.f, 0.f, 0.f, 0.f);
        }
    };
    // convert + store registers into smem buffer
    auto sts_chunk = [&](int buf) {
#pragma unroll
        for (int p = 0; p < 4; p++) {
            float4 v = pA[p];
            if (RELU) {
                v.x = fmaxf(v.x, 0.f); v.y = fmaxf(v.y, 0.f);
                v.z = fmaxf(v.z, 0.f); v.w = fmaxf(v.w, 0.f);
            }
            uint4 u = make_uint4(cvt_tf32(v.x), cvt_tf32(v.y), cvt_tf32(v.z), cvt_tf32(v.w));
            *(uint4*)&smu[buf * AS_BUF + (arow + p * 32) * AS_STRIDE + ac4] = u;
        }
#pragma unroll
        for (int p = 0; p < 2; p++) {
            float4 w4 = pB[p];
            uint4 hi; uint4 lo;
#pragma unroll
            for (int u = 0; u < 4; u++) {
                float    wv = ((float*)&w4)[u];
                uint32_t hb = __float_as_uint(wv) & 0xFFFFE000u;  // exact tf32 value
                ((uint32_t*)&hi)[u] = hb;
                ((uint32_t*)&lo)[u] = cvt_tf32(wv - __uint_as_float(hb));
            }
            int kk = bk + p * 16;
            *(uint4*)&smu[BH_OFF + buf * BS_BUF + kk * BS_STRIDE + bn4] = hi;
            *(uint4*)&smu[BL_OFF + buf * BS_BUF + kk * BS_STRIDE + bn4] = lo;
        }
    };
    auto compute = [&](int buf) {
        const uint32_t* Ab = &smu[buf * AS_BUF];
        const uint32_t* Hb = &smu[BH_OFF + buf * BS_BUF];
        const uint32_t* Lb = &smu[BL_OFF + buf * BS_BUF];
        const int lr = lane >> 2, lc = lane & 3;
#pragma unroll
        for (int ks = 0; ks < 4; ks++) {
            uint32_t af[2][4];
#pragma unroll
            for (int t = 0; t < 2; t++) {
                int r = wm * 32 + t * 16 + lr;
                int c = ks * 8 + lc;
                af[t][0] = Ab[r * AS_STRIDE + c];
                af[t][1] = Ab[(r + 8) * AS_STRIDE + c];
                af[t][2] = Ab[r * AS_STRIDE + c + 4];
                af[t][3] = Ab[(r + 8) * AS_STRIDE + c + 4];
            }
            uint32_t bh[4][2], bl[4][2];
#pragma unroll
            for (int j = 0; j < 4; j++) {
                int n = wn * 32 + j * 8 + lr;
                int k = ks * 8 + lc;
                bh[j][0] = Hb[k * BS_STRIDE + n];
                bh[j][1] = Hb[(k + 4) * BS_STRIDE + n];
                bl[j][0] = Lb[k * BS_STRIDE + n];
                bl[j][1] = Lb[(k + 4) * BS_STRIDE + n];
            }
#pragma unroll
            for (int t = 0; t < 2; t++)
#pragma unroll
                for (int j = 0; j < 4; j++) {
                    MMA_TF32(acc[t][j], af[t], bh[j]);
                    MMA_TF32(acc[t][j], af[t], bl[j]);
                }
        }
    };

    ldg_chunk(0);
    sts_chunk(0);
    __syncthreads();
    for (int c = 0; c < Kchunks; c++) {
        if (c + 1 < Kchunks) ldg_chunk(c + 1);
        compute(c & 1);
        if (c + 1 < Kchunks) {
            sts_chunk((c + 1) & 1);
            __syncthreads();
        }
    }

    // ---- epilogue ----
    const int lr = lane >> 2, lc = lane & 3;
#pragma unroll
    for (int t = 0; t < 2; t++) {
        size_t r0 = m0 + wm * 32 + t * 16 + lr;
        size_t r1 = r0 + 8;
        float sn0 = 1.f, sn1 = 1.f;
        if (r0 < NN) { float dv = g_dinv[r0]; sn0 = dv * dv; }
        if (r1 < NN) { float dv = g_dinv[r1]; sn1 = dv * dv; }
#pragma unroll
        for (int j = 0; j < 4; j++) {
            int col = n0 + wn * 32 + j * 8 + lc * 2;
            float b0 = (col     < HID) ? bias[col]     : 0.f;
            float b1 = (col + 1 < HID) ? bias[col + 1] : 0.f;
            float c0 = acc[t][j][0], c1 = acc[t][j][1];
            float c2 = acc[t][j][2], c3 = acc[t][j][3];
            *(float2*)(out + r0 * PAD + col) = make_float2(fmaf(sn0, c0, b0), fmaf(sn0, c1, b1));
            *(float2*)(out + r1 * PAD + col) = make_float2(fmaf(sn1, c2, b0), fmaf(sn1, c3, b1));
            if (r0 < NN) *(float2*)(g_hwS + r0 * PAD + col) = make_float2(c0, c1);
            if (r1 < NN) *(float2*)(g_hwS + r1 * PAD + col) = make_float2(c2, c3);
        }
    }
}

// ---------------- CSR gather: out[node] += sum val * hw[src] ----------------
__global__ __launch_bounds__(256)
void k_gather(float* __restrict__ out) {
    int w = (blockIdx.x * 256 + threadIdx.x) >> 5;
    int lane = threadIdx.x & 31;
    if (w >= NN * 10) return;
    int node = w / 10, seg = w % 10;
    int j = seg * 32 + lane;
    int s = g_rowptr[node], e = g_rowptr[node + 1];
    float acc = out[(size_t)node * PAD + j];
    for (int p = s; p < e; p++)
        acc = fmaf(g_val[p], g_hwS[(size_t)g_src[p] * PAD + j], acc);
    out[(size_t)node * PAD + j] = acc;
}

// ---------------- readout ----------------
__global__ void k_mean(const float* __restrict__ h) {
    int j = threadIdx.x;  // 320
    size_t r0 = (size_t)blockIdx.x * 256;
    float acc = 0.f;
    for (int r = 0; r < 256; r++)
        acc += fmaxf(h[(r0 + r) * PAD + j], 0.f);
    g_part[blockIdx.x * PAD + j] = acc;
}
__global__ void k_head(const float* __restrict__ w1, const float* __restrict__ b1,
                       const float* __restrict__ w2, const float* __restrict__ b2,
                       float* __restrict__ out) {
    __shared__ float g[PAD];
    __shared__ float t1[32];
    int t = threadIdx.x;  // 320
    if (t < PAD) {
        float s = 0.f;
        for (int b = 0; b < 625; b++) s += g_part[b * PAD + t];
        g[t] = s * (1.0f / (float)MRWS);
    }
    __syncthreads();
    if (t < 32) {
        float a = b1[t];
        for (int j = 0; j < HID; j++) a = fmaf(g[j], w1[j * 32 + t], a);
        t1[t] = fmaxf(a, 0.f);
    }
    __syncthreads();
    if (t < 2) {
        float a = b2[t];
        for (int k = 0; k < 32; k++) a = fmaf(t1[k], w2[k * 2 + t], a);
        out[t] = a;
    }
}

// ---------------- launch ----------------
extern "C" void kernel_launch(void* const* d_in, const int* in_sizes, int n_in,
                              void* d_out, int out_size) {
    const int*   ei        = (const int*)d_in[1];
    const float* edge_attr = (const float*)d_in[2];
    const float* edge_w    = (const float*)d_in[6];
    const float* edge_b    = (const float*)d_in[7];
    const float* gcn0_w    = (const float*)d_in[8];
    const float* gcn0_b    = (const float*)d_in[9];
    const float* gcn_w     = (const float*)d_in[10];
    const float* gcn_b     = (const float*)d_in[11];
    const float* lin1_w    = (const float*)d_in[12];
    const float* lin1_b    = (const float*)d_in[13];
    const float* lin2_w    = (const float*)d_in[14];
    const float* lin2_b    = (const float*)d_in[15];
    float* out = (float*)d_out;

    cudaFuncSetAttribute(k_gemm<0>, cudaFuncAttributeMaxDynamicSharedMemorySize, SM_WORDS * 4);
    cudaFuncSetAttribute(k_gemm<1>, cudaFuncAttributeMaxDynamicSharedMemorySize, SM_WORDS * 4);

    float *bufA = nullptr, *bufB = nullptr;
    cudaGetSymbolAddress((void**)&bufA, g_bufA);
    cudaGetSymbolAddress((void**)&bufB, g_bufB);

    k_init<<<40, 256>>>();
    k_count<<<625, 256>>>(ei);
    k_dinv<<<40, 256>>>();
    k_scan<<<1, 1024>>>();
    k_fillidx<<<625, 256>>>(ei);
    k_sortnode<<<40, 256>>>(ei);
    k_edge_embed<<<20000, 256>>>(edge_attr, edge_w, edge_b);

    dim3 ggrid(1250, 5);

    // layer 0: K=32 (1 chunk), no input relu
    k_gemm<0><<<ggrid, 256, SM_WORDS * 4>>>(bufA, gcn0_w, gcn0_b, bufB, 1, LDIM);
    k_gather<<<12500, 256>>>(bufB);

    // layers 1..4: K=300 -> 10 chunks, relu on input
    for (int l = 1; l < 5; l++) {
        const float* in = (l & 1) ? bufB : bufA;
        float*       o  = (l & 1) ? bufA : bufB;
        k_gemm<1><<<ggrid, 256, SM_WORDS * 4>>>(in, gcn_w + (size_t)(l - 1) * HID * HID,
                                                gcn_b + (size_t)(l - 1) * HID, o, 10, HID);
        k_gather<<<12500, 256>>>(o);
    }

    k_mean<<<625, 320>>>(bufB);
    k_head<<<1, 320>>>(lin1_w, lin1_b, lin2_w, lin2_b, out);
}

// round 4
// speedup vs baseline: 3.5626x; 1.5558x over previous
#include <cuda_runtime.h>
#include <cuda_fp16.h>
#include <cstdint>
#include <cstddef>

#define NE    160000
#define NN    10000
#define HID   300
#define PAD   320
#define LDIM  32
#define MRWS  160000

// ---------------- scratch (static __device__, allocation-free) ----------------
__device__ float  g_bufA[(size_t)MRWS * PAD];   // 204.8 MB
__device__ float  g_bufB[(size_t)MRWS * PAD];   // 204.8 MB
__device__ float  g_hwS[(size_t)NN * PAD];      // 12.8 MB raw hw, rows < NN
__device__ __half g_BT[(size_t)5 * 2 * PAD * PAD];  // weights: [layer][hi/lo][n][k]
__device__ int    g_cnt[NN];
__device__ float  g_dinv[NN];
__device__ int    g_rowptr[NN + 1];
__device__ int    g_fill[NN];
__device__ int    g_eid[NE];
__device__ int    g_src[NE];
__device__ float  g_val[NE];
__device__ float  g_part[625 * PAD];

#define MMA_F16(c, a, b)                                                      \
    asm volatile("mma.sync.aligned.m16n8k16.row.col.f32.f16.f16.f32 "         \
        "{%0,%1,%2,%3}, {%4,%5,%6,%7}, {%8,%9}, {%0,%1,%2,%3};"               \
        : "+f"((c)[0]), "+f"((c)[1]), "+f"((c)[2]), "+f"((c)[3])              \
        : "r"((a)[0]), "r"((a)[1]), "r"((a)[2]), "r"((a)[3]),                 \
          "r"((b)[0]), "r"((b)[1]))

// ---------------- prep kernels ----------------
__global__ void k_init() {
    int i = blockIdx.x * blockDim.x + threadIdx.x;
    if (i < NN) { g_cnt[i] = 0; g_fill[i] = 0; }
}
__global__ void k_count(const int* __restrict__ ei) {
    int e = blockIdx.x * blockDim.x + threadIdx.x;
    if (e < NE) atomicAdd(&g_cnt[ei[NE + e]], 1);
}
__global__ void k_dinv() {
    int i = blockIdx.x * blockDim.x + threadIdx.x;
    if (i < NN) g_dinv[i] = rsqrtf((float)(g_cnt[i] + 1));
}
__global__ void k_scan() {
    __shared__ int sm[1024];
    int t = threadIdx.x;
    int v[10]; int loc = 0;
#pragma unroll
    for (int u = 0; u < 10; u++) {
        int idx = t * 10 + u;
        v[u] = (idx < NN) ? g_cnt[idx] : 0;
        loc += v[u];
    }
    sm[t] = loc; __syncthreads();
    for (int off = 1; off < 1024; off <<= 1) {
        int add = (t >= off) ? sm[t - off] : 0;
        __syncthreads();
        sm[t] += add;
        __syncthreads();
    }
    int run = sm[t] - loc;
#pragma unroll
    for (int u = 0; u < 10; u++) {
        int idx = t * 10 + u;
        if (idx < NN) { g_rowptr[idx] = run; run += v[u]; }
    }
    if (t == 0) g_rowptr[NN] = NE;
}
__global__ void k_fillidx(const int* __restrict__ ei) {
    int e = blockIdx.x * blockDim.x + threadIdx.x;
    if (e >= NE) return;
    int c = ei[NE + e];
    int p = atomicAdd(&g_fill[c], 1);
    g_eid[g_rowptr[c] + p] = e;
}
// deterministic per-node ordering: sort edge ids ascending
__global__ void k_sortnode(const int* __restrict__ ei) {
    int i = blockIdx.x * blockDim.x + threadIdx.x;
    if (i >= NN) return;
    int s = g_rowptr[i], d = g_rowptr[i + 1] - s;
    if (d <= 128) {
        int ids[128];
        for (int q = 0; q < d; q++) ids[q] = g_eid[s + q];
        for (int q = 1; q < d; q++) {
            int key = ids[q], p = q - 1;
            while (p >= 0 && ids[p] > key) { ids[p + 1] = ids[p]; p--; }
            ids[p + 1] = key;
        }
        for (int q = 0; q < d; q++) g_eid[s + q] = ids[q];
    } else {
        for (int q = 1; q < d; q++) {
            int key = g_eid[s + q], p = q - 1;
            while (p >= 0 && g_eid[s + p] > key) { g_eid[s + p + 1] = g_eid[s + p]; p--; }
            g_eid[s + p + 1] = key;
        }
    }
    float di = g_dinv[i];
    for (int q = 0; q < d; q++) {
        int e = g_eid[s + q];
        int r = ei[e];
        g_src[s + q] = r;
        g_val[s + q] = g_dinv[r] * di;
    }
}
__global__ void k_edge_embed(const float* __restrict__ attr,
                             const float* __restrict__ w,
                             const float* __restrict__ b) {
    int idx = blockIdx.x * blockDim.x + threadIdx.x;
    if (idx >= NE * LDIM) return;
    int e = idx >> 5, j = idx & 31;
    float a0 = attr[e * 3 + 0], a1 = attr[e * 3 + 1], a2 = attr[e * 3 + 2];
    g_bufA[(size_t)e * PAD + j] = b[j] + a0 * w[j] + a1 * w[32 + j] + a2 * w[64 + j];
}
// Pre-split all layer weights into fp16 hi/lo, transposed [n][k], padded to 320.
__global__ void k_prepB(const float* __restrict__ gcn0_w, const float* __restrict__ gcn_w) {
    int idx = blockIdx.x * blockDim.x + threadIdx.x;   // 5*320*320
    int l   = idx / (PAD * PAD);
    int rem = idx % (PAD * PAD);
    int n   = rem / PAD;
    int k   = rem % PAD;
    int kt  = (l == 0) ? LDIM : HID;
    float w = 0.f;
    if (k < kt && n < HID)
        w = (l == 0) ? gcn0_w[k * HID + n]
                     : gcn_w[(size_t)(l - 1) * HID * HID + k * HID + n];
    __half hi = __float2half_rn(w);
    __half lo = __float2half_rn(w - __half2float(hi));
    size_t base = (size_t)l * 2 * PAD * PAD;
    g_BT[base + (size_t)n * PAD + k]             = hi;
    g_BT[base + (size_t)PAD * PAD + (size_t)n * PAD + k] = lo;
}

// ---------------- fp16 mma.sync GEMM (compensated weights) ----------------
// BM=128, BN=64, Kchunk=32 (2 x k16 steps), 256 threads (8 warps 4x2),
// warp tile 32x32.  out = self_norm(m)*C + bias ; raw C -> g_hwS for m < NN.
// smem word layout (32-bit units):
//   A   : 2 bufs x 128 rows x 20 words (32 fp16 + pad)      [0    .. 5120)
//   Bhi : 2 bufs x  64 rows x 20 words                      [5120 .. 7680)
//   Blo : 2 bufs x  64 rows x 20 words                      [7680 .. 10240)
#define AW_STR   20
#define A_BUFW   (128 * AW_STR)     // 2560
#define BH_OFF   (2 * A_BUFW)       // 5120
#define BL_OFF   (BH_OFF + 2 * 64 * AW_STR)  // 7680
#define SMW      (BL_OFF + 2 * 64 * AW_STR)  // 10240 words = 40960 B

template <int RELU>
__global__ __launch_bounds__(256)
void k_gemm(const float* __restrict__ A, const __half* __restrict__ BT,
            const float* __restrict__ bias, float* __restrict__ out, int Kchunks) {
    extern __shared__ uint32_t smu[];
    const int tid  = threadIdx.x;
    const int wid  = tid >> 5, lane = tid & 31;
    const int wm   = wid & 3, wn = wid >> 2;
    const size_t m0 = (size_t)blockIdx.x * 128;
    const int    n0 = blockIdx.y * 64;

    float acc[2][4][4];
#pragma unroll
    for (int t = 0; t < 2; t++)
#pragma unroll
        for (int j = 0; j < 4; j++)
#pragma unroll
            for (int q = 0; q < 4; q++) acc[t][j][q] = 0.f;

    float4 pA[4];
    uint4  pB[2];
    const int arow = tid >> 3, ac4 = (tid & 7) * 4;

    auto ldg_chunk = [&](int c) {
        int k0 = c * 32;
#pragma unroll
        for (int p = 0; p < 4; p++)
            pA[p] = *(const float4*)(A + (m0 + arow + p * 32) * PAD + k0 + ac4);
#pragma unroll
        for (int u = 0; u < 2; u++) {
            int gid = tid + u * 256;                  // 0..511
            int mat = gid >> 8, rem = gid & 255;
            int n = rem >> 2, kw4 = (rem & 3) * 8;    // 8 halves
            pB[u] = *(const uint4*)(BT + (size_t)mat * PAD * PAD +
                                    (size_t)(n0 + n) * PAD + k0 + kw4);
        }
    };
    auto sts_chunk = [&](int buf) {
#pragma unroll
        for (int p = 0; p < 4; p++) {
            float4 v = pA[p];
            if (RELU) {
                v.x = fmaxf(v.x, 0.f); v.y = fmaxf(v.y, 0.f);
                v.z = fmaxf(v.z, 0.f); v.w = fmaxf(v.w, 0.f);
            }
            uint2 h;
            h.x = __half2uint_rn(0), h.x = 0;  // placate compiler init
            __half2 h01 = __floats2half2_rn(v.x, v.y);
            __half2 h23 = __floats2half2_rn(v.z, v.w);
            h.x = *(uint32_t*)&h01; h.y = *(uint32_t*)&h23;
            *(uint2*)&smu[buf * A_BUFW + (arow + p * 32) * AW_STR + ac4 / 2] = h;
        }
#pragma unroll
        for (int u = 0; u < 2; u++) {
            int gid = tid + u * 256;
            int mat = gid >> 8, rem = gid & 255;
            int n = rem >> 2, kw4 = (rem & 3) * 4;    // words
            int off = (mat ? BL_OFF : BH_OFF) + buf * 64 * AW_STR + n * AW_STR + kw4;
            *(uint4*)&smu[off] = pB[u];
        }
    };
    auto compute = [&](int buf) {
        const uint32_t* Ab = &smu[buf * A_BUFW];
        const uint32_t* Hb = &smu[BH_OFF + buf * 64 * AW_STR];
        const uint32_t* Lb = &smu[BL_OFF + buf * 64 * AW_STR];
        const int lr = lane >> 2, lc = lane & 3;
#pragma unroll
        for (int ks = 0; ks < 2; ks++) {
            uint32_t af[2][4];
#pragma unroll
            for (int t = 0; t < 2; t++) {
                int r = wm * 32 + t * 16 + lr;
                int cw = ks * 8 + lc;
                af[t][0] = Ab[r * AW_STR + cw];
                af[t][1] = Ab[(r + 8) * AW_STR + cw];
                af[t][2] = Ab[r * AW_STR + cw + 4];
                af[t][3] = Ab[(r + 8) * AW_STR + cw + 4];
            }
            uint32_t bh[4][2], bl[4][2];
#pragma unroll
            for (int j = 0; j < 4; j++) {
                int n = wn * 32 + j * 8 + lr;
                int cw = ks * 8 + lc;
                bh[j][0] = Hb[n * AW_STR + cw];
                bh[j][1] = Hb[n * AW_STR + cw + 4];
                bl[j][0] = Lb[n * AW_STR + cw];
                bl[j][1] = Lb[n * AW_STR + cw + 4];
            }
#pragma unroll
            for (int t = 0; t < 2; t++)
#pragma unroll
                for (int j = 0; j < 4; j++) {
                    MMA_F16(acc[t][j], af[t], bh[j]);
                    MMA_F16(acc[t][j], af[t], bl[j]);
                }
        }
    };

    ldg_chunk(0);
    sts_chunk(0);
    __syncthreads();
    for (int c = 0; c < Kchunks; c++) {
        if (c + 1 < Kchunks) ldg_chunk(c + 1);
        compute(c & 1);
        if (c + 1 < Kchunks) {
            sts_chunk((c + 1) & 1);
            __syncthreads();
        }
    }

    // ---- epilogue ----
    const int lr = lane >> 2, lc = lane & 3;
#pragma unroll
    for (int t = 0; t < 2; t++) {
        size_t r0 = m0 + wm * 32 + t * 16 + lr;
        size_t r1 = r0 + 8;
        float sn0 = 1.f, sn1 = 1.f;
        if (r0 < NN) { float dv = g_dinv[r0]; sn0 = dv * dv; }
        if (r1 < NN) { float dv = g_dinv[r1]; sn1 = dv * dv; }
#pragma unroll
        for (int j = 0; j < 4; j++) {
            int col = n0 + wn * 32 + j * 8 + lc * 2;
            float b0 = (col     < HID) ? bias[col]     : 0.f;
            float b1 = (col + 1 < HID) ? bias[col + 1] : 0.f;
            float c0 = acc[t][j][0], c1 = acc[t][j][1];
            float c2 = acc[t][j][2], c3 = acc[t][j][3];
            *(float2*)(out + r0 * PAD + col) = make_float2(fmaf(sn0, c0, b0), fmaf(sn0, c1, b1));
            *(float2*)(out + r1 * PAD + col) = make_float2(fmaf(sn1, c2, b0), fmaf(sn1, c3, b1));
            if (r0 < NN) *(float2*)(g_hwS + r0 * PAD + col) = make_float2(c0, c1);
            if (r1 < NN) *(float2*)(g_hwS + r1 * PAD + col) = make_float2(c2, c3);
        }
    }
}

// ---------------- CSR gather: out[node] += sum val * hw[src] ----------------
__global__ __launch_bounds__(256)
void k_gather(float* __restrict__ out) {
    int w = (blockIdx.x * 256 + threadIdx.x) >> 5;
    int lane = threadIdx.x & 31;
    if (w >= NN * 10) return;
    int node = w / 10, seg = w % 10;
    int j = seg * 32 + lane;
    int s = g_rowptr[node], e = g_rowptr[node + 1];
    float acc = out[(size_t)node * PAD + j];
    for (int p = s; p < e; p++)
        acc = fmaf(g_val[p], g_hwS[(size_t)g_src[p] * PAD + j], acc);
    out[(size_t)node * PAD + j] = acc;
}

// ---------------- readout ----------------
__global__ void k_mean(const float* __restrict__ h) {
    int j = threadIdx.x;  // 320
    size_t r0 = (size_t)blockIdx.x * 256;
    float acc = 0.f;
    for (int r = 0; r < 256; r++)
        acc += fmaxf(h[(r0 + r) * PAD + j], 0.f);
    g_part[blockIdx.x * PAD + j] = acc;
}
__global__ void k_head(const float* __restrict__ w1, const float* __restrict__ b1,
                       const float* __restrict__ w2, const float* __restrict__ b2,
                       float* __restrict__ out) {
    __shared__ float g[PAD];
    __shared__ float t1[32];
    int t = threadIdx.x;  // 320
    if (t < PAD) {
        float s = 0.f;
        for (int b = 0; b < 625; b++) s += g_part[b * PAD + t];
        g[t] = s * (1.0f / (float)MRWS);
    }
    __syncthreads();
    if (t < 32) {
        float a = b1[t];
        for (int j = 0; j < HID; j++) a = fmaf(g[j], w1[j * 32 + t], a);
        t1[t] = fmaxf(a, 0.f);
    }
    __syncthreads();
    if (t < 2) {
        float a = b2[t];
        for (int k = 0; k < 32; k++) a = fmaf(t1[k], w2[k * 2 + t], a);
        out[t] = a;
    }
}

// ---------------- launch ----------------
extern "C" void kernel_launch(void* const* d_in, const int* in_sizes, int n_in,
                              void* d_out, int out_size) {
    const int*   ei        = (const int*)d_in[1];
    const float* edge_attr = (const float*)d_in[2];
    const float* edge_w    = (const float*)d_in[6];
    const float* edge_b    = (const float*)d_in[7];
    const float* gcn0_w    = (const float*)d_in[8];
    const float* gcn0_b    = (const float*)d_in[9];
    const float* gcn_w     = (const float*)d_in[10];
    const float* gcn_b     = (const float*)d_in[11];
    const float* lin1_w    = (const float*)d_in[12];
    const float* lin1_b    = (const float*)d_in[13];
    const float* lin2_w    = (const float*)d_in[14];
    const float* lin2_b    = (const float*)d_in[15];
    float* out = (float*)d_out;

    cudaFuncSetAttribute(k_gemm<0>, cudaFuncAttributeMaxDynamicSharedMemorySize, SMW * 4);
    cudaFuncSetAttribute(k_gemm<1>, cudaFuncAttributeMaxDynamicSharedMemorySize, SMW * 4);

    float *bufA = nullptr, *bufB = nullptr;
    __half* bt = nullptr;
    cudaGetSymbolAddress((void**)&bufA, g_bufA);
    cudaGetSymbolAddress((void**)&bufB, g_bufB);
    cudaGetSymbolAddress((void**)&bt, g_BT);

    k_init<<<40, 256>>>();
    k_count<<<625, 256>>>(ei);
    k_dinv<<<40, 256>>>();
    k_scan<<<1, 1024>>>();
    k_fillidx<<<625, 256>>>(ei);
    k_sortnode<<<40, 256>>>(ei);
    k_prepB<<<2000, 256>>>(gcn0_w, gcn_w);
    k_edge_embed<<<20000, 256>>>(edge_attr, edge_w, edge_b);

    dim3 ggrid(1250, 5);
    const size_t LSZ = (size_t)2 * PAD * PAD;

    // layer 0: K=32 (1 chunk), no input relu
    k_gemm<0><<<ggrid, 256, SMW * 4>>>(bufA, bt, gcn0_b, bufB, 1);
    k_gather<<<12500, 256>>>(bufB);

    // layers 1..4: K=300 -> 10 chunks, relu on input
    for (int l = 1; l < 5; l++) {
        const float* in = (l & 1) ? bufB : bufA;
        float*       o  = (l & 1) ? bufA : bufB;
        k_gemm<1><<<ggrid, 256, SMW * 4>>>(in, bt + (size_t)l * LSZ,
                                           gcn_b + (size_t)(l - 1) * HID, o, 10);
        k_gather<<<12500, 256>>>(o);
    }

    k_mean<<<625, 320>>>(bufB);
    k_head<<<1, 320>>>(lin1_w, lin1_b, lin2_w, lin2_b, out);
}